// round 4
// baseline (speedup 1.0000x reference)
#include <cuda_runtime.h>
#include <cub/cub.cuh>

// Problem constants (fixed shapes)
#define NCLS 19
#define NPIX (1 << 21)          // 8*512*512 = 2,097,152
#define HW   (1 << 18)          // 512*512
#define NTOT (NCLS * NPIX)      // 39,845,888
#define CHUNK 4096
#define CPC  (NPIX / CHUNK)     // 512 chunks per class
#define NCHUNK (NTOT / CHUNK)   // 9728

// Scratch (device globals; no allocations allowed).
__device__ alignas(256) unsigned int  g_keysA[NTOT];
__device__ alignas(256) unsigned int  g_keysB[NTOT];
__device__ alignas(256) unsigned char g_temp[128u << 20];   // 128 MB CUB temp
__device__ alignas(256) unsigned int  g_chunkFg[NCHUNK];
__device__ alignas(256) unsigned int  g_chunkBase[NCHUNK];
__device__ unsigned int  g_classG[NCLS];
__device__ double        g_dot[NCLS];
__device__ double        g_se[NCLS];

#define INV_Q 5.9604644775390625e-8f   // 2^-24

__global__ void zero_acc_kernel() {
    int t = threadIdx.x;
    if (t < NCLS) { g_dot[t] = 0.0; g_se[t] = 0.0; }
}

// Softmax + error + 32-bit key:  key = (class<<25) | (q24<<1) | fg
// NOTE: target is int32 (JAX silently downcasts int64 -> int32 with x64 off).
__global__ void compute_keys_kernel(const float* __restrict__ logits,
                                    const int* __restrict__ target,
                                    unsigned int* __restrict__ keys) {
    int n = blockIdx.x * blockDim.x + threadIdx.x;   // pixel id, exact grid
    int b  = n >> 18;
    int hw = n & (HW - 1);
    const float* lp = logits + ((size_t)b * NCLS) * HW + hw;

    float v[NCLS];
    float m = -3.4e38f;
#pragma unroll
    for (int c = 0; c < NCLS; c++) { v[c] = lp[(size_t)c * HW]; m = fmaxf(m, v[c]); }
    float s = 0.f;
#pragma unroll
    for (int c = 0; c < NCLS; c++) { v[c] = __expf(v[c] - m); s += v[c]; }
    float inv = 1.0f / s;
    int t = target[n];
#pragma unroll
    for (int c = 0; c < NCLS; c++) {
        float p = v[c] * inv;
        unsigned fg = (t == c) ? 1u : 0u;
        float e = fg ? (1.0f - p) : p;
        unsigned q = __float2uint_rn(e * 16777216.0f);
        if (q > 16777215u) q = 16777215u;
        keys[((size_t)c << 21) + n] = ((unsigned)c << 25) | (q << 1) | fg;
    }
}

// Per-chunk fg population count over the sorted keys
__global__ void chunk_count_kernel(const unsigned int* __restrict__ keys) {
    __shared__ unsigned int sred[8];
    size_t base = (size_t)blockIdx.x * CHUNK + (size_t)threadIdx.x * 16;
    const uint4* p = reinterpret_cast<const uint4*>(keys + base);
    unsigned cnt = 0;
#pragma unroll
    for (int k = 0; k < 4; k++) {
        uint4 u = p[k];
        cnt += (u.x & 1) + (u.y & 1) + (u.z & 1) + (u.w & 1);
    }
#pragma unroll
    for (int o = 16; o; o >>= 1) cnt += __shfl_down_sync(0xffffffffu, cnt, o);
    if ((threadIdx.x & 31) == 0) sred[threadIdx.x >> 5] = cnt;
    __syncthreads();
    if (threadIdx.x == 0) {
        unsigned tt = 0;
#pragma unroll
        for (int w = 0; w < 8; w++) tt += sred[w];
        g_chunkFg[blockIdx.x] = tt;
    }
}

// Per-class exclusive scan of chunk counts (512 chunks/class, one block each)
__global__ void scan_chunks_kernel() {
    __shared__ unsigned int s[CPC];
    int c = blockIdx.x, t = threadIdx.x;
    unsigned cnt = g_chunkFg[c * CPC + t];
    s[t] = cnt;
    __syncthreads();
    for (int off = 1; off < CPC; off <<= 1) {
        unsigned v = (t >= off) ? s[t - off] : 0u;
        __syncthreads();
        s[t] += v;
        __syncthreads();
    }
    g_chunkBase[c * CPC + t] = s[t] - cnt;
    if (t == CPC - 1) g_classG[c] = s[t];
}

// Main loss scan: for each sorted element j (ascending), with P = #fg before j,
// weight w = 1 - P/(NPIX - j + P); accumulate dot += e*w and se += e per class.
__global__ void scan_loss_kernel(const unsigned int* __restrict__ keys) {
    __shared__ unsigned int sscan[256];
    __shared__ float sdot[8], sse[8];
    int chunk = blockIdx.x;
    int cls = chunk >> 9;            // / CPC
    int cic = chunk & (CPC - 1);
    size_t base = (size_t)chunk * CHUNK + (size_t)threadIdx.x * 16;
    const uint4* p = reinterpret_cast<const uint4*>(keys + base);
    unsigned lk[16];
    uint4 u;
    u = p[0]; lk[0]=u.x; lk[1]=u.y; lk[2]=u.z; lk[3]=u.w;
    u = p[1]; lk[4]=u.x; lk[5]=u.y; lk[6]=u.z; lk[7]=u.w;
    u = p[2]; lk[8]=u.x; lk[9]=u.y; lk[10]=u.z; lk[11]=u.w;
    u = p[3]; lk[12]=u.x; lk[13]=u.y; lk[14]=u.z; lk[15]=u.w;

    unsigned myFg = 0;
#pragma unroll
    for (int t = 0; t < 16; t++) myFg += lk[t] & 1u;

    sscan[threadIdx.x] = myFg;
    __syncthreads();
    for (int off = 1; off < 256; off <<= 1) {
        unsigned v = (threadIdx.x >= off) ? sscan[threadIdx.x - off] : 0u;
        __syncthreads();
        sscan[threadIdx.x] += v;
        __syncthreads();
    }
    unsigned P = g_chunkBase[chunk] + (sscan[threadIdx.x] - myFg);

    unsigned jbase = ((unsigned)cic << 12) + (unsigned)threadIdx.x * 16u;
    float se = 0.f, dot = 0.f;
#pragma unroll
    for (int t = 0; t < 16; t++) {
        unsigned k = lk[t];
        unsigned fg = k & 1u;
        float e = (float)((k >> 1) & 0xFFFFFFu) * INV_Q;
        unsigned jj = jbase + (unsigned)t;
        float un = (float)(NPIX - jj + P);          // < 2^23: exact in f32
        float w = 1.0f - __fdividef((float)P, un);
        dot += e * w;
        se  += e;
        P += fg;
    }
#pragma unroll
    for (int o = 16; o; o >>= 1) {
        dot += __shfl_down_sync(0xffffffffu, dot, o);
        se  += __shfl_down_sync(0xffffffffu, se, o);
    }
    if ((threadIdx.x & 31) == 0) {
        sdot[threadIdx.x >> 5] = dot;
        sse[threadIdx.x >> 5]  = se;
    }
    __syncthreads();
    if (threadIdx.x == 0) {
        float td = 0.f, ts = 0.f;
#pragma unroll
        for (int w = 0; w < 8; w++) { td += sdot[w]; ts += sse[w]; }
        atomicAdd(&g_dot[cls], (double)td);
        atomicAdd(&g_se[cls],  (double)ts);
    }
}

// loss_c = dot_c - j1*(Se_c - e_top);  mean over present classes
__global__ void finalize_kernel(const unsigned int* __restrict__ keys,
                                float* __restrict__ out) {
    int c = threadIdx.x;
    double lc = 0.0, pres = 0.0;
    if (c < NCLS) {
        unsigned G = g_classG[c];
        if (G > 0) {
            unsigned ktop = keys[((size_t)(c + 1) << 21) - 1];
            unsigned fgtop = ktop & 1u;
            double etop = (double)((ktop >> 1) & 0xFFFFFFu) * (double)INV_Q;
            double P1 = (double)(G - fgtop);
            double j1 = 1.0 - P1 / (P1 + 1.0);
            lc = g_dot[c] - j1 * (g_se[c] - etop);
            pres = 1.0;
        }
    }
#pragma unroll
    for (int o = 16; o; o >>= 1) {
        lc   += __shfl_down_sync(0xffffffffu, lc, o);
        pres += __shfl_down_sync(0xffffffffu, pres, o);
    }
    if (c == 0) out[0] = (float)(lc / pres);
}

extern "C" void kernel_launch(void* const* d_in, const int* in_sizes, int n_in,
                              void* d_out, int out_size) {
    const float* logits = (const float*)d_in[0];
    const int* target = (const int*)d_in[1];   // int32 (JAX x64 disabled)
    float* out = (float*)d_out;

    unsigned int *dA = nullptr, *dB = nullptr;
    void* dT = nullptr;
    cudaGetSymbolAddress((void**)&dA, g_keysA);
    cudaGetSymbolAddress((void**)&dB, g_keysB);
    cudaGetSymbolAddress(&dT, g_temp);

    zero_acc_kernel<<<1, 32>>>();
    compute_keys_kernel<<<NPIX / 256, 256>>>(logits, target, dA);

    cub::DoubleBuffer<unsigned int> db(dA, dB);
    size_t temp_bytes = 0;
    cub::DeviceRadixSort::SortKeys(nullptr, temp_bytes, db, NTOT, 0, 30);
    if (temp_bytes <= sizeof(g_temp)) {
        cub::DeviceRadixSort::SortKeys(dT, temp_bytes, db, NTOT, 0, 30);
    }
    const unsigned int* sorted = db.Current();

    chunk_count_kernel<<<NCHUNK, 256>>>(sorted);
    scan_chunks_kernel<<<NCLS, CPC>>>();
    scan_loss_kernel<<<NCHUNK, 256>>>(sorted);
    finalize_kernel<<<1, 32>>>(sorted, out);
}

// round 7
// speedup vs baseline: 3.2157x; 3.2157x over previous
#include <cuda_runtime.h>
#include <math.h>

// Fixed shapes
#define NCLS 19
#define NPIX (1u << 21)         // 8*512*512 pixels
#define HW   (1 << 18)          // 512*512
#define NTOT (NCLS * (1u << 21))
#define NQ   32768              // 15-bit error buckets
#define NT   256                // tiles per class (128 q / 256 k per tile)
#define SLICES 8
#define SL_PIX (NPIX / SLICES)  // 262144
#define INV_Q15 3.0517578125e-5 // 2^-15

// Scratch (device globals; no allocations anywhere)
__device__ alignas(256) unsigned short g_keys[NTOT];          // 80 MB
__device__ alignas(256) unsigned int   g_bgH[NCLS * NQ];      // bg histograms
__device__ alignas(256) unsigned int   g_fgH[NCLS * NQ];      // fg histograms
__device__ alignas(256) unsigned int   g_tileN[NCLS * NT];
__device__ alignas(256) unsigned int   g_tileF[NCLS * NT];
__device__ alignas(256) unsigned int   g_tileBJ[NCLS * NT];
__device__ alignas(256) unsigned int   g_tileBP[NCLS * NT];
__device__ unsigned int g_lastK[NCLS];
__device__ unsigned int g_classG[NCLS];
__device__ double g_dot[NCLS], g_se[NCLS];

// -------- zero scratch --------
__global__ void zero_kernel() {
    unsigned i = blockIdx.x * blockDim.x + threadIdx.x;
    unsigned total = NCLS * NQ;
    for (unsigned k = i; k < total; k += gridDim.x * blockDim.x) {
        g_bgH[k] = 0u; g_fgH[k] = 0u;
    }
    if (i < NCLS) { g_dot[i] = 0.0; g_se[i] = 0.0; g_lastK[i] = 0u; g_classG[i] = 0u; }
}

// -------- A: softmax -> u16 key = (q15<<1)|fg ; fg counts via global REDG ----
__global__ void compute_keys_kernel(const float* __restrict__ logits,
                                    const int* __restrict__ target,
                                    unsigned short* __restrict__ keys) {
    unsigned n = blockIdx.x * blockDim.x + threadIdx.x;   // pixel id (exact grid)
    int b  = n >> 18;
    int hw = n & (HW - 1);
    const float* lp = logits + ((size_t)b * NCLS) * HW + hw;

    float v[NCLS];
    float m = -3.4e38f;
#pragma unroll
    for (int c = 0; c < NCLS; c++) { v[c] = lp[(size_t)c * HW]; m = fmaxf(m, v[c]); }
    float s = 0.f;
#pragma unroll
    for (int c = 0; c < NCLS; c++) { v[c] = __expf(v[c] - m); s += v[c]; }
    float inv = 1.0f / s;
    int t = target[n];
#pragma unroll
    for (int c = 0; c < NCLS; c++) {
        float p = v[c] * inv;
        unsigned fg = (t == c) ? 1u : 0u;
        float e = fg ? (1.0f - p) : p;
        unsigned q = __float2uint_rn(e * 32768.0f);
        if (q > 32767u) q = 32767u;
        keys[((size_t)c << 21) + n] = (unsigned short)((q << 1) | fg);
        if (fg) atomicAdd(&g_fgH[c * NQ + q], 1u);   // 2M total, spread
    }
}

// -------- B: per-(class,slice) smem bg histogram --------
extern __shared__ unsigned int sh_hist[];   // NQ u32 = 128 KB dynamic
__global__ void hist_kernel(const unsigned short* __restrict__ keys) {
    int cls = blockIdx.y, slice = blockIdx.x, tid = threadIdx.x;
    for (int q = tid; q < NQ; q += 256) sh_hist[q] = 0u;
    __syncthreads();

    size_t base = (size_t)cls * NPIX + (size_t)slice * SL_PIX;
    const uint4* p = reinterpret_cast<const uint4*>(keys + base);
    const int nvec = SL_PIX / 8;            // 32768 uint4 per slice
    for (int i = tid; i < nvec; i += 256) {
        uint4 u = p[i];
        unsigned w;
        w = u.x; { unsigned k = w & 0xFFFFu; if (!(k & 1u)) atomicAdd(&sh_hist[k >> 1], 1u); }
                 { unsigned k = w >> 16;     if (!(k & 1u)) atomicAdd(&sh_hist[k >> 1], 1u); }
        w = u.y; { unsigned k = w & 0xFFFFu; if (!(k & 1u)) atomicAdd(&sh_hist[k >> 1], 1u); }
                 { unsigned k = w >> 16;     if (!(k & 1u)) atomicAdd(&sh_hist[k >> 1], 1u); }
        w = u.z; { unsigned k = w & 0xFFFFu; if (!(k & 1u)) atomicAdd(&sh_hist[k >> 1], 1u); }
                 { unsigned k = w >> 16;     if (!(k & 1u)) atomicAdd(&sh_hist[k >> 1], 1u); }
        w = u.w; { unsigned k = w & 0xFFFFu; if (!(k & 1u)) atomicAdd(&sh_hist[k >> 1], 1u); }
                 { unsigned k = w >> 16;     if (!(k & 1u)) atomicAdd(&sh_hist[k >> 1], 1u); }
    }
    __syncthreads();
    for (int q = tid; q < NQ; q += 256) {
        unsigned v = sh_hist[q];
        if (v) atomicAdd(&g_bgH[cls * NQ + q], v);
    }
}

// -------- C1: per-tile totals + per-class last nonempty bucket --------
__global__ void tile_sum_kernel() {
    __shared__ unsigned int smax[256];
    int c = blockIdx.x, t = threadIdx.x;
    unsigned n = 0, f = 0, last = 0;
    for (int i = 0; i < 128; i++) {
        int q = t * 128 + i;
        unsigned bg = g_bgH[c * NQ + q];
        unsigned fg = g_fgH[c * NQ + q];
        n += bg + fg; f += fg;
        unsigned lk = fg ? (unsigned)(2 * q + 1) : (bg ? (unsigned)(2 * q) : 0u);
        if (lk > last) last = lk;
    }
    g_tileN[c * NT + t] = n;
    g_tileF[c * NT + t] = f;
    smax[t] = last;
    __syncthreads();
    for (int off = 128; off; off >>= 1) {
        if (t < off) smax[t] = max(smax[t], smax[t + off]);
        __syncthreads();
    }
    if (t == 0) g_lastK[c] = smax[0];
}

// -------- C2: per-class exclusive scan of tile totals --------
__global__ void tile_scan_kernel() {
    __shared__ unsigned long long s[NT];
    int c = blockIdx.x, t = threadIdx.x;
    unsigned long long v = ((unsigned long long)g_tileF[c * NT + t] << 32)
                         | (unsigned long long)g_tileN[c * NT + t];
    s[t] = v;
    __syncthreads();
    for (int off = 1; off < NT; off <<= 1) {
        unsigned long long u = (t >= off) ? s[t - off] : 0ull;
        __syncthreads();
        s[t] += u;
        __syncthreads();
    }
    unsigned long long ex = s[t] - v;
    g_tileBJ[c * NT + t] = (unsigned)(ex & 0xFFFFFFFFull);
    g_tileBP[c * NT + t] = (unsigned)(ex >> 32);
    if (t == NT - 1) g_classG[c] = (unsigned)(s[t] >> 32);
}

// H(b) - H(a) = sum_{k=a+1}^{b} 1/k ; exact loop for small a, digamma asymptotic above
__device__ double hsum(unsigned a, unsigned b) {
    double s = 0.0;
    while (a < b && a < 1024u) { a++; s += 1.0 / (double)a; }
    if (a < b) {
        double da = (double)a, db = (double)b;
        s += log(db / da) + 0.5 * (1.0 / db - 1.0 / da)
           - (1.0 / 12.0) * (1.0 / (db * db) - 1.0 / (da * da));
    }
    return s;
}

// -------- C3: per-bucket closed-form Lovasz contributions --------
__global__ void bucket_loss_kernel() {
    __shared__ unsigned long long s[256];
    __shared__ double sd[8], ss[8];
    int c = blockIdx.y, t = blockIdx.x, b = threadIdx.x;
    int k = t * 256 + b;
    int q = k >> 1, f = k & 1;
    unsigned n = f ? g_fgH[c * NQ + q] : g_bgH[c * NQ + q];

    unsigned long long v = ((unsigned long long)(f ? n : 0u) << 32)
                         | (unsigned long long)n;
    s[b] = v;
    __syncthreads();
    for (int off = 1; off < 256; off <<= 1) {
        unsigned long long u = (b >= off) ? s[b - off] : 0ull;
        __syncthreads();
        s[b] += u;
        __syncthreads();
    }
    unsigned long long ex = s[b] - v;
    unsigned j0 = g_tileBJ[c * NT + t] + (unsigned)(ex & 0xFFFFFFFFull);
    unsigned P0 = g_tileBP[c * NT + t] + (unsigned)(ex >> 32);

    double e = (double)q * INV_Q15;
    double contrib = 0.0, se_l = 0.0;
    if (n) {
        se_l = e * (double)n;
        if (f) {
            double D0 = (double)(NPIX - j0 + P0);   // union, constant over run
            double dn = (double)n;
            contrib = e * (dn - (dn * (double)P0 + 0.5 * dn * (dn - 1.0)) / D0);
        } else if (P0) {
            unsigned D0i = NPIX + P0 - j0;
            double S = hsum(D0i - n, D0i);
            contrib = e * ((double)n - (double)P0 * S);
        } else {
            contrib = e * (double)n;                // weight == 1
        }
    }
#pragma unroll
    for (int o = 16; o; o >>= 1) {
        contrib += __shfl_down_sync(0xffffffffu, contrib, o);
        se_l    += __shfl_down_sync(0xffffffffu, se_l, o);
    }
    if ((b & 31) == 0) { sd[b >> 5] = contrib; ss[b >> 5] = se_l; }
    __syncthreads();
    if (b == 0) {
        double td = 0.0, ts = 0.0;
#pragma unroll
        for (int w = 0; w < 8; w++) { td += sd[w]; ts += ss[w]; }
        atomicAdd(&g_dot[c], td);
        atomicAdd(&g_se[c], ts);
    }
}

// -------- finalize: loss_c = dot - j1*(se - e_top); mean over present --------
__global__ void finalize_kernel(float* __restrict__ out) {
    int c = threadIdx.x;
    double lc = 0.0, pres = 0.0;
    if (c < NCLS) {
        unsigned G = g_classG[c];
        if (G > 0) {
            unsigned k = g_lastK[c];
            double etop = (double)(k >> 1) * INV_Q15;
            unsigned fgtop = k & 1u;
            double P1 = (double)(G - fgtop);
            double j1 = 1.0 - P1 / (P1 + 1.0);
            lc = g_dot[c] - j1 * (g_se[c] - etop);
            pres = 1.0;
        }
    }
#pragma unroll
    for (int o = 16; o; o >>= 1) {
        lc   += __shfl_down_sync(0xffffffffu, lc, o);
        pres += __shfl_down_sync(0xffffffffu, pres, o);
    }
    if (c == 0) out[0] = (float)(lc / pres);
}

extern "C" void kernel_launch(void* const* d_in, const int* in_sizes, int n_in,
                              void* d_out, int out_size) {
    const float* logits = (const float*)d_in[0];
    const int* target = (const int*)d_in[1];   // int32 (JAX x64 disabled)
    float* out = (float*)d_out;

    unsigned short* dK = nullptr;
    cudaGetSymbolAddress((void**)&dK, g_keys);

    // 128 KB dynamic smem for the histogram kernel (idempotent host config)
    cudaFuncSetAttribute(hist_kernel,
                         cudaFuncAttributeMaxDynamicSharedMemorySize, NQ * 4);

    zero_kernel<<<2048, 256>>>();
    compute_keys_kernel<<<NPIX / 256, 256>>>(logits, target, dK);
    hist_kernel<<<dim3(SLICES, NCLS), 256, NQ * 4>>>(dK);
    tile_sum_kernel<<<NCLS, 256>>>();
    tile_scan_kernel<<<NCLS, NT>>>();
    bucket_loss_kernel<<<dim3(NT, NCLS), 256>>>();
    finalize_kernel<<<1, 32>>>(out);
}

// round 8
// speedup vs baseline: 4.5407x; 1.4120x over previous
#include <cuda_runtime.h>
#include <math.h>

// Fixed shapes
#define NCLS 19
#define NPIX (1u << 21)          // 8*512*512 pixels
#define HW   (1 << 18)           // 512*512
#define NQ   2048                // 11-bit error buckets
#define CH   (NCLS * NQ)         // 38912 = 152*256 exactly
#define FB   152                 // fused blocks = one per SM (GB300: 152 SMs)
#define PPB  13798               // ceil(NPIX / FB)
#define INV_Q 4.8828125e-4       // 1/2048

// Scratch (device globals; no allocations anywhere)
__device__ alignas(256) unsigned int g_blockHist[FB][CH];   // ~23.7 MB
__device__ alignas(256) unsigned int g_bgH[CH];
__device__ alignas(256) unsigned int g_fgH[CH];
__device__ double g_loss[NCLS];
__device__ int    g_pres[NCLS];

// -------- zero fg histogram (bg block-hists are fully overwritten) --------
__global__ void zero_kernel() {
    unsigned j = blockIdx.x * blockDim.x + threadIdx.x;   // grid covers CH exactly
    g_fgH[j] = 0u;
}

// -------- fused softmax + per-class error histogram --------
// One CTA per SM; 19 class histograms (152 KB) live in this CTA's smem.
extern __shared__ unsigned int sh[];   // CH u32
__global__ __launch_bounds__(256) void fused_hist_kernel(
        const float* __restrict__ logits, const int* __restrict__ target) {
    int tid = threadIdx.x;
    for (int j = tid; j < CH; j += 256) sh[j] = 0u;
    __syncthreads();

    unsigned start = blockIdx.x * PPB;
    unsigned end = start + PPB; if (end > NPIX) end = NPIX;
    for (unsigned n = start + tid; n < end; n += 256) {
        int b = n >> 18, hw = n & (HW - 1);
        const float* lp = logits + ((size_t)b * NCLS) * HW + hw;
        float v[NCLS];
        float m = -3.4e38f;
#pragma unroll
        for (int c = 0; c < NCLS; c++) { v[c] = lp[(size_t)c * HW]; m = fmaxf(m, v[c]); }
        float s = 0.f;
#pragma unroll
        for (int c = 0; c < NCLS; c++) { v[c] = __expf(v[c] - m); s += v[c]; }
        float inv = 1.0f / s;
        int t = target[n];
#pragma unroll
        for (int c = 0; c < NCLS; c++) {
            float p = v[c] * inv;
            if (t == c) {                        // rare (1/19): global REDG
                unsigned q = __float2uint_rn((1.0f - p) * 2048.0f);
                if (q > 2047u) q = 2047u;
                atomicAdd(&g_fgH[c * NQ + q], 1u);
            } else {
                unsigned q = __float2uint_rn(p * 2048.0f);
                if (q > 2047u) q = 2047u;
                atomicAdd(&sh[c * NQ + q], 1u);
            }
        }
    }
    __syncthreads();
    unsigned int* outp = g_blockHist[blockIdx.x];
    for (int j = tid; j < CH; j += 256) outp[j] = sh[j];
}

// -------- merge per-block bg histograms (coalesced) --------
__global__ void merge_kernel() {   // grid 152 x 256 covers CH exactly
    unsigned j = blockIdx.x * 256 + threadIdx.x;
    unsigned s = 0;
#pragma unroll 8
    for (int b = 0; b < FB; b++) s += g_blockHist[b][j];
    g_bgH[j] = s;
}

// H(b) - H(a) = sum_{k=a+1}^{b} 1/k ; exact loop small, digamma asymptotic above
__device__ double hsum(unsigned a, unsigned b) {
    double s = 0.0;
    while (a < b && a < 1024u) { a++; s += 1.0 / (double)a; }
    if (a < b) {
        double da = (double)a, db = (double)b;
        s += log(db / da) + 0.5 * (1.0 / db - 1.0 / da)
           - (1.0 / 12.0) * (1.0 / (db * db) - 1.0 / (da * da));
    }
    return s;
}

// -------- per-class: scan slots + closed-form Lovasz + loss --------
// Slots s = 2q+f, ascending error; bg (f=0) before fg (f=1) within a bucket.
__global__ __launch_bounds__(1024) void class_loss_kernel() {
    __shared__ unsigned long long sscan[1024];
    __shared__ unsigned int smax[1024];
    __shared__ double sdot[32], sse[32];
    __shared__ unsigned long long s_tot;
    int c = blockIdx.x, t = threadIdx.x;

    unsigned nn[4];
    unsigned nt = 0, ft = 0, last = 0;
#pragma unroll
    for (int i = 0; i < 4; i++) {
        int s = t * 4 + i, q = s >> 1, f = s & 1;
        unsigned v = f ? g_fgH[c * NQ + q] : g_bgH[c * NQ + q];
        nn[i] = v; nt += v; if (f) ft += v;
        if (v) last = (unsigned)s;
    }
    sscan[t] = ((unsigned long long)ft << 32) | (unsigned long long)nt;
    smax[t] = last;
    __syncthreads();

    // Hillis-Steele inclusive scan over 1024 threads
    for (int off = 1; off < 1024; off <<= 1) {
        unsigned long long u = (t >= off) ? sscan[t - off] : 0ull;
        __syncthreads();
        sscan[t] += u;
        __syncthreads();
    }
    if (t == 1023) s_tot = sscan[1023];
    unsigned long long ex = sscan[t] - (((unsigned long long)ft << 32) | nt);
    unsigned j0 = (unsigned)(ex & 0xFFFFFFFFull);
    unsigned P0 = (unsigned)(ex >> 32);

    // block max of last nonempty slot
    __syncthreads();
    for (int off = 512; off; off >>= 1) {
        if (t < off) smax[t] = max(smax[t], smax[t + off]);
        __syncthreads();
    }

    // closed-form contributions for this thread's 4 slots
    double dot = 0.0, se = 0.0;
#pragma unroll
    for (int i = 0; i < 4; i++) {
        int s = t * 4 + i, q = s >> 1, f = s & 1;
        unsigned n = nn[i];
        if (n) {
            double e = (double)q * INV_Q;
            double dn = (double)n;
            se += e * dn;
            if (f) {   // fg run: union constant D0
                double D0 = (double)(NPIX - j0 + P0);
                dot += e * (dn - (dn * (double)P0 + 0.5 * dn * (dn - 1.0)) / D0);
            } else if (P0) {   // bg run: harmonic sum
                unsigned D0i = NPIX + P0 - j0;
                dot += e * (dn - (double)P0 * hsum(D0i - n, D0i));
            } else {
                dot += e * dn;   // weight == 1
            }
        }
        j0 += n; if (f) P0 += n;
    }
#pragma unroll
    for (int o = 16; o; o >>= 1) {
        dot += __shfl_down_sync(0xffffffffu, dot, o);
        se  += __shfl_down_sync(0xffffffffu, se, o);
    }
    if ((t & 31) == 0) { sdot[t >> 5] = dot; sse[t >> 5] = se; }
    __syncthreads();
    if (t == 0) {
        double td = 0.0, ts = 0.0;
#pragma unroll
        for (int w = 0; w < 32; w++) { td += sdot[w]; ts += sse[w]; }
        unsigned G = (unsigned)(s_tot >> 32);
        if (G > 0) {
            unsigned ks = smax[0];
            double etop = (double)(ks >> 1) * INV_Q;
            unsigned fgtop = ks & 1u;
            double P1 = (double)(G - fgtop);
            double j1 = 1.0 - P1 / (P1 + 1.0);
            g_loss[c] = td - j1 * (ts - etop);
            g_pres[c] = 1;
        } else {
            g_loss[c] = 0.0;
            g_pres[c] = 0;
        }
    }
}

// -------- mean over present classes --------
__global__ void mean_kernel(float* __restrict__ out) {
    int c = threadIdx.x;
    double lc = 0.0, pres = 0.0;
    if (c < NCLS && g_pres[c]) { lc = g_loss[c]; pres = 1.0; }
#pragma unroll
    for (int o = 16; o; o >>= 1) {
        lc   += __shfl_down_sync(0xffffffffu, lc, o);
        pres += __shfl_down_sync(0xffffffffu, pres, o);
    }
    if (c == 0) out[0] = (float)(lc / pres);
}

extern "C" void kernel_launch(void* const* d_in, const int* in_sizes, int n_in,
                              void* d_out, int out_size) {
    const float* logits = (const float*)d_in[0];
    const int* target = (const int*)d_in[1];   // int32 (JAX x64 disabled)
    float* out = (float*)d_out;

    cudaFuncSetAttribute(fused_hist_kernel,
                         cudaFuncAttributeMaxDynamicSharedMemorySize, CH * 4);

    zero_kernel<<<FB, 256>>>();
    fused_hist_kernel<<<FB, 256, CH * 4>>>(logits, target);
    merge_kernel<<<FB, 256>>>();
    class_loss_kernel<<<NCLS, 1024>>>();
    mean_kernel<<<1, 32>>>(out);
}

// round 9
// speedup vs baseline: 8.7016x; 1.9164x over previous
#include <cuda_runtime.h>
#include <math.h>

// Fixed shapes
#define NCLS 19
#define NPIX (1u << 21)          // 8*512*512 pixels
#define HW   (1 << 18)           // 512*512
#define NQ   2048                // 11-bit error buckets
#define CH   (NCLS * NQ)         // 38912 = 152*256 exactly
#define FB   152                 // fused blocks = one per SM (GB300: 152 SMs)
#define PPB  13798               // ceil(NPIX / FB)
#define INV_Q 4.8828125e-4f      // 1/2048

// Scratch (device globals; no allocations anywhere)
__device__ alignas(256) unsigned short g_blockHist[FB][CH];  // ~11.9 MB (u16: cnt<=PPB)
__device__ alignas(256) unsigned int   g_bgH[CH];
__device__ alignas(256) unsigned int   g_fgH[CH];
__device__ double g_loss[NCLS];
__device__ int    g_pres[NCLS];

// -------- zero fg histogram (bg block-hists are fully overwritten) --------
__global__ void zero_kernel() {
    unsigned j = blockIdx.x * blockDim.x + threadIdx.x;   // grid covers CH exactly
    g_fgH[j] = 0u;
}

// -------- fused softmax + per-class error histogram --------
// One CTA per SM; 19 class histograms (152 KB) live in this CTA's smem.
extern __shared__ unsigned int sh[];   // CH u32
__global__ __launch_bounds__(512) void fused_hist_kernel(
        const float* __restrict__ logits, const int* __restrict__ target) {
    int tid = threadIdx.x;
    for (int j = tid; j < CH; j += 512) sh[j] = 0u;
    __syncthreads();

    unsigned start = blockIdx.x * PPB;
    unsigned end = start + PPB; if (end > NPIX) end = NPIX;
    for (unsigned n = start + tid; n < end; n += 512) {
        int b = n >> 18, hw = n & (HW - 1);
        const float* lp = logits + ((size_t)b * NCLS) * HW + hw;
        float v[NCLS];
        float m = -3.4e38f;
#pragma unroll
        for (int c = 0; c < NCLS; c++) { v[c] = lp[(size_t)c * HW]; m = fmaxf(m, v[c]); }
        float s = 0.f;
#pragma unroll
        for (int c = 0; c < NCLS; c++) { v[c] = __expf(v[c] - m); s += v[c]; }
        float inv = 1.0f / s;
        int t = target[n];
#pragma unroll
        for (int c = 0; c < NCLS; c++) {
            float p = v[c] * inv;
            if (t == c) {                        // rare (1/19): global REDG
                unsigned q = __float2uint_rn((1.0f - p) * 2048.0f);
                if (q > 2047u) q = 2047u;
                atomicAdd(&g_fgH[c * NQ + q], 1u);
            } else {
                unsigned q = __float2uint_rn(p * 2048.0f);
                if (q > 2047u) q = 2047u;
                atomicAdd(&sh[c * NQ + q], 1u);
            }
        }
    }
    __syncthreads();
    unsigned short* outp = g_blockHist[blockIdx.x];
    for (int j = tid; j < CH; j += 512) outp[j] = (unsigned short)sh[j];
}

// -------- merge per-block bg histograms (coalesced u16 reads) --------
__global__ void merge_kernel() {   // grid 152 x 256 covers CH exactly
    unsigned j = blockIdx.x * 256 + threadIdx.x;
    unsigned s = 0;
#pragma unroll 8
    for (int b = 0; b < FB; b++) s += (unsigned)g_blockHist[b][j];
    g_bgH[j] = s;
}

// H(b)-H(a), b = a+n, in f32.  a is always >= ~1e5 here (union >= class
// cardinality), so the digamma asymptotic applies; correction terms are
// computed in product form to avoid cancellation. Tiny-a fallback loop kept
// for safety.
__device__ __forceinline__ float hsum_f(float da, float dn) {
    float db = da + dn;
    if (da < 32.0f) {
        float s = 0.f;
        for (float k = da + 1.0f; k <= db; k += 1.0f) s += __fdividef(1.0f, k);
        return s;
    }
    float inv_ab = __fdividef(1.0f, da * db);
    return log1pf(__fdividef(dn, da))
         - 0.5f * dn * inv_ab
         + (1.0f / 12.0f) * dn * (da + db) * inv_ab * inv_ab;
}

// -------- per-class: scan slots + closed-form Lovasz + loss --------
// Slots s = 2q+f, ascending error; bg (f=0) before fg (f=1) within a bucket.
__global__ __launch_bounds__(1024) void class_loss_kernel() {
    __shared__ unsigned long long sscan[1024];
    __shared__ unsigned int smax[1024];
    __shared__ double sdot[32], sse[32];
    __shared__ unsigned long long s_tot;
    int c = blockIdx.x, t = threadIdx.x;

    unsigned nn[4];
    unsigned nt = 0, ft = 0, last = 0;
#pragma unroll
    for (int i = 0; i < 4; i++) {
        int s = t * 4 + i, q = s >> 1, f = s & 1;
        unsigned v = f ? g_fgH[c * NQ + q] : g_bgH[c * NQ + q];
        nn[i] = v; nt += v; if (f) ft += v;
        if (v) last = (unsigned)s;
    }
    sscan[t] = ((unsigned long long)ft << 32) | (unsigned long long)nt;
    smax[t] = last;
    __syncthreads();

    for (int off = 1; off < 1024; off <<= 1) {
        unsigned long long u = (t >= off) ? sscan[t - off] : 0ull;
        __syncthreads();
        sscan[t] += u;
        __syncthreads();
    }
    if (t == 1023) s_tot = sscan[1023];
    unsigned long long ex = sscan[t] - (((unsigned long long)ft << 32) | nt);
    unsigned j0 = (unsigned)(ex & 0xFFFFFFFFull);
    unsigned P0 = (unsigned)(ex >> 32);

    __syncthreads();
    for (int off = 512; off; off >>= 1) {
        if (t < off) smax[t] = max(smax[t], smax[t + off]);
        __syncthreads();
    }

    double dot = 0.0, se = 0.0;
#pragma unroll
    for (int i = 0; i < 4; i++) {
        int s = t * 4 + i, q = s >> 1, f = s & 1;
        unsigned n = nn[i];
        if (n) {
            float e = (float)q * INV_Q;
            float dn = (float)n;
            se += (double)(e * dn);
            if (f) {   // fg run: union constant D0 (arithmetic series)
                float D0 = (float)(NPIX - j0 + P0);
                float num = dn * (float)P0 + 0.5f * dn * (dn - 1.0f);
                dot += (double)(e * (dn - __fdividef(num, D0)));
            } else if (P0) {   // bg run: harmonic difference
                float D0f = (float)(NPIX + P0 - j0);
                float S = hsum_f(D0f - dn, dn);
                dot += (double)(e * (dn - (float)P0 * S));
            } else {
                dot += (double)(e * dn);   // weight == 1
            }
        }
        j0 += n; if (f) P0 += n;
    }
#pragma unroll
    for (int o = 16; o; o >>= 1) {
        dot += __shfl_down_sync(0xffffffffu, dot, o);
        se  += __shfl_down_sync(0xffffffffu, se, o);
    }
    if ((t & 31) == 0) { sdot[t >> 5] = dot; sse[t >> 5] = se; }
    __syncthreads();
    if (t == 0) {
        double td = 0.0, ts = 0.0;
#pragma unroll
        for (int w = 0; w < 32; w++) { td += sdot[w]; ts += sse[w]; }
        unsigned G = (unsigned)(s_tot >> 32);
        if (G > 0) {
            unsigned ks = smax[0];
            double etop = (double)(ks >> 1) * (double)INV_Q;
            unsigned fgtop = ks & 1u;
            double P1 = (double)(G - fgtop);
            double j1 = 1.0 - P1 / (P1 + 1.0);
            g_loss[c] = td - j1 * (ts - etop);
            g_pres[c] = 1;
        } else {
            g_loss[c] = 0.0;
            g_pres[c] = 0;
        }
    }
}

// -------- mean over present classes --------
__global__ void mean_kernel(float* __restrict__ out) {
    int c = threadIdx.x;
    double lc = 0.0, pres = 0.0;
    if (c < NCLS && g_pres[c]) { lc = g_loss[c]; pres = 1.0; }
#pragma unroll
    for (int o = 16; o; o >>= 1) {
        lc   += __shfl_down_sync(0xffffffffu, lc, o);
        pres += __shfl_down_sync(0xffffffffu, pres, o);
    }
    if (c == 0) out[0] = (float)(lc / pres);
}

extern "C" void kernel_launch(void* const* d_in, const int* in_sizes, int n_in,
                              void* d_out, int out_size) {
    const float* logits = (const float*)d_in[0];
    const int* target = (const int*)d_in[1];   // int32 (JAX x64 disabled)
    float* out = (float*)d_out;

    cudaFuncSetAttribute(fused_hist_kernel,
                         cudaFuncAttributeMaxDynamicSharedMemorySize, CH * 4);

    zero_kernel<<<FB, 256>>>();
    fused_hist_kernel<<<FB, 512, CH * 4>>>(logits, target);
    merge_kernel<<<FB, 256>>>();
    class_loss_kernel<<<NCLS, 1024>>>();
    mean_kernel<<<1, 32>>>(out);
}